// round 17
// baseline (speedup 1.0000x reference)
#include <cuda_runtime.h>
#include <cuda_fp16.h>
#include <cstdint>

// out = LeakyReLU( D^-1 * (A @ (X @ W^T)) + b ),  B=32, N=1024, F=128
//
// k_xw  : XW = X @ W^T fp16 mma. W fp32 cp.async'd straight into smem;
//         B frags built via LDS.64 + pack (same pattern as A frags) — no
//         separate conversion kernel. Output fp16 [m][o].
// k_main: C = A @ XW fp16 mma, BM=128, BK=64, 2-stage cp.async pipeline
//         (R16, proven). deg = rowsum(A) FADD balanced across all warps.

#define NEG_SLOPE 0.01f

__device__ __half g_xw[32u * 1024u * 128u];  // fp16 XW [m][o] (8 MB)

// ---------------- helpers ----------------
__device__ __forceinline__ uint32_t su32(const void* p) {
    uint32_t r;
    asm("{\n\t.reg .u64 t;\n\tcvta.to.shared.u64 t, %1;\n\tcvt.u32.u64 %0, t;\n\t}"
        : "=r"(r) : "l"(p));
    return r;
}
__device__ __forceinline__ void cp16(uint32_t dst, const void* src) {
    asm volatile("cp.async.cg.shared.global [%0], [%1], 16;" :: "r"(dst), "l"(src));
}
__device__ __forceinline__ void cp_commit() {
    asm volatile("cp.async.commit_group;" ::: "memory");
}
template <int N>
__device__ __forceinline__ void cp_wait() {
    asm volatile("cp.async.wait_group %0;" :: "n"(N) : "memory");
}
__device__ __forceinline__ void mma_f16(float* c, const uint32_t* a, const uint32_t* b) {
    asm volatile(
        "mma.sync.aligned.m16n8k16.row.col.f32.f16.f16.f32 "
        "{%0,%1,%2,%3}, {%4,%5,%6,%7}, {%8,%9}, {%0,%1,%2,%3};"
        : "+f"(c[0]), "+f"(c[1]), "+f"(c[2]), "+f"(c[3])
        : "r"(a[0]), "r"(a[1]), "r"(a[2]), "r"(a[3]), "r"(b[0]), "r"(b[1]));
}
__device__ __forceinline__ void ldmat4t(uint32_t* r, uint32_t addr) {
    asm volatile(
        "ldmatrix.sync.aligned.m8n8.x4.trans.shared.b16 {%0,%1,%2,%3}, [%4];"
        : "=r"(r[0]), "=r"(r[1]), "=r"(r[2]), "=r"(r[3]) : "r"(addr));
}
__device__ __forceinline__ uint32_t pack_h2(float lo, float hi) {
    uint32_t r;
    asm("cvt.rn.f16x2.f32 %0, %2, %1;" : "=r"(r) : "f"(lo), "f"(hi));
    return r;
}
__device__ __forceinline__ float leaky(float v) {
    return (v >= 0.0f) ? v : NEG_SLOPE * v;
}

// =====================================================================
// k_xw: XW = X @ W^T (fp16 mma). grid=512 (m-tiles 64), 256 thr, 8 warps:
// wr=wid&3 (m16 each), wc=wid>>2 (n64 each). Whole tiles resident:
// smem: Wf fp32 [128][136] (69632B) | Xs fp32 [64][136] (34816B).
// B frags: 2x LDS.64 + 2x pack per n8 tile (layout dual of A frags).
// =====================================================================
#define XW_SMEM (69632 + 34816)

__global__ __launch_bounds__(256) void k_xw(const float* __restrict__ X,
                                            const float* __restrict__ W) {
    extern __shared__ char smx[];
    const float2* Wf2 = (const float2*)smx;
    const uint32_t wf_a = su32(smx), xs_a = su32(smx + 69632);
    const float2* Xs2 = (const float2*)(smx + 69632);

    const int tid = threadIdx.x, lane = tid & 31, wid = tid >> 5;
    const int g = lane >> 2, tig = lane & 3;
    const int wr = wid & 3, wc = wid >> 2;
    const int m0 = blockIdx.x * 64;

    // W fp32 [o=128][f=128] -> [128][136]: 4096 chunks of 16B, 16/thread
#pragma unroll
    for (int i = 0; i < 16; i++) {
        int ch = tid + i * 256;
        int r = ch >> 5, c = ch & 31;
        cp16(wf_a + (uint32_t)(r * 544 + c * 16), W + r * 128 + c * 4);
    }
    // X fp32 [64][128] -> [64][136]: 2048 chunks, 8/thread
#pragma unroll
    for (int i = 0; i < 8; i++) {
        int ch = tid + i * 256;
        int r = ch >> 5, c = ch & 31;
        cp16(xs_a + (uint32_t)(r * 544 + c * 16),
             X + (size_t)(m0 + r) * 128 + c * 4);
    }
    cp_commit();
    cp_wait<0>();
    __syncthreads();

    float acc[8][4];
#pragma unroll
    for (int ni = 0; ni < 8; ni++)
#pragma unroll
        for (int q = 0; q < 4; q++) acc[ni][q] = 0.0f;

#pragma unroll
    for (int s = 0; s < 8; s++) {
        // A frags (proven pattern): LDS.64 pairs from Xs, stride 68 float2
        int base = (wr * 16 + g) * 68 + s * 8 + tig;
        float2 u0 = Xs2[base];
        float2 u1 = Xs2[base + 8 * 68];
        float2 u2 = Xs2[base + 4];
        float2 u3 = Xs2[base + 8 * 68 + 4];
        uint32_t a[4] = {pack_h2(u0.x, u0.y), pack_h2(u1.x, u1.y),
                         pack_h2(u2.x, u2.y), pack_h2(u3.x, u3.y)};
#pragma unroll
        for (int j = 0; j < 8; j++) {  // n8 tiles
            int o = wc * 64 + j * 8 + g;
            int bidx = o * 68 + s * 8 + tig;
            float2 w0 = Wf2[bidx];      // k = s*16 + 2tig, +1
            float2 w1 = Wf2[bidx + 4];  // k = s*16 + 2tig + 8, +9
            uint32_t b[2] = {pack_h2(w0.x, w0.y), pack_h2(w1.x, w1.y)};
            mma_f16(acc[j], a, b);
        }
    }

    // epilogue: fp16 [m][o]  (acc[ni] covers n8 tile at wc*64 + ni*8)
    uint32_t* outp = (uint32_t*)g_xw;
    const int row = m0 + wr * 16 + g;
#pragma unroll
    for (int ni = 0; ni < 8; ni++) {
        int col2 = wc * 32 + ni * 4 + tig;
        outp[(size_t)row * 64 + col2] = pack_h2(acc[ni][0], acc[ni][1]);
        outp[(size_t)(row + 8) * 64 + col2] = pack_h2(acc[ni][2], acc[ni][3]);
    }
}

// =====================================================================
// k_main (R16, proven): per batch C = A @ XW (fp16 mma), BM=128, BK=64;
// grid (8,32), 256 thr, 8 warps: wr=wid&3 (m32), wc=wid>>2 (n64).
// smem: As 2 x [128][72] fp32 (73728B) | Bs 2 x [64][136] fp16 (34816B)
// deg: all warps accumulate (wc pair computes identical sums; benign
// duplicate writes), removing the wc==0 straggler imbalance.
// =====================================================================
#define AP2 72
#define AS2B 73728
#define BS2B 34816
#define MAIN_SMEM (AS2B + BS2B + 512)

__global__ __launch_bounds__(256, 2) void k_main(const float* __restrict__ A,
                                                 const float* __restrict__ bias,
                                                 float* __restrict__ out) {
    extern __shared__ float sm[];
    char* smc = (char*)sm;
    const float2* As2 = (const float2*)sm;
    float* degs = (float*)(smc + AS2B + BS2B);
    const uint32_t as_a = su32(sm), bs_a = su32(smc + AS2B);

    const int tid = threadIdx.x, lane = tid & 31, wid = tid >> 5;
    const int g = lane >> 2, tig = lane & 3;
    const int wr = wid & 3, wc = wid >> 2;
    const int m0 = blockIdx.x * 128, bz = blockIdx.y;
    const float* Ab = A + (size_t)bz * 1024 * 1024;
    const __half* Bp = g_xw + (size_t)bz * 131072;

    auto loadT = [&](int buf, int s) {
#pragma unroll
        for (int i = 0; i < 8; i++) {
            int gi = tid + i * 256;
            int r = gi >> 4, c = gi & 15;
            cp16(as_a + (uint32_t)(((buf * 128 + r) * AP2 + c * 4) * 4),
                 Ab + (size_t)(m0 + r) * 1024 + s * 64 + c * 4);
        }
        const char* src = (const char*)(Bp + s * 8192);
#pragma unroll
        for (int i = 0; i < 4; i++) {
            int gi = tid + i * 256;
            int r = gi >> 4, c = gi & 15;
            cp16(bs_a + (uint32_t)(buf * 17408 + r * 272 + c * 16),
                 src + r * 256 + c * 16);
        }
        cp_commit();
    };

    float acc[2][8][4];
#pragma unroll
    for (int mi = 0; mi < 2; mi++)
#pragma unroll
        for (int ni = 0; ni < 8; ni++)
#pragma unroll
            for (int q = 0; q < 4; q++) acc[mi][ni][q] = 0.0f;
    float dg[2][2] = {{0.0f, 0.0f}, {0.0f, 0.0f}};

    loadT(0, 0);

    const int lm_k = lane & 15;
    const int lm_n8 = (lane >> 4) * 8;

    for (int s = 0; s < 16; s++) {
        if (s < 15) { loadT((s + 1) & 1, s + 1); cp_wait<1>(); }
        else cp_wait<0>();
        __syncthreads();
        const int buf = s & 1;
        const uint32_t bsb = bs_a + buf * 17408;

#pragma unroll
        for (int h = 0; h < 4; h++) {  // four k16 halves of the k64 stage
            uint32_t a[2][4];
#pragma unroll
            for (int mi = 0; mi < 2; mi++) {
                int row = wr * 32 + mi * 16 + g;
                int base = (buf * 128 + row) * (AP2 / 2) + h * 8 + tig;
                float2 u0 = As2[base];
                float2 u1 = As2[base + 8 * (AP2 / 2)];
                float2 u2 = As2[base + 4];
                float2 u3 = As2[base + 8 * (AP2 / 2) + 4];
                a[mi][0] = pack_h2(u0.x, u0.y);
                a[mi][1] = pack_h2(u1.x, u1.y);
                a[mi][2] = pack_h2(u2.x, u2.y);
                a[mi][3] = pack_h2(u3.x, u3.y);
                // balanced: both wc warps of a wr pair compute identical sums
                dg[mi][0] += (u0.x + u0.y) + (u2.x + u2.y);
                dg[mi][1] += (u1.x + u1.y) + (u3.x + u3.y);
            }
            uint32_t bfr[4][4];
#pragma unroll
            for (int j = 0; j < 4; j++) {
                int n0 = wc * 64 + j * 16 + lm_n8;
                ldmat4t(bfr[j], bsb + (uint32_t)((h * 16 + lm_k) * 272 + n0 * 2));
            }
#pragma unroll
            for (int ni = 0; ni < 8; ni++) {
                const uint32_t* b = &bfr[ni >> 1][(ni & 1) * 2];
                mma_f16(acc[0][ni], a[0], b);
                mma_f16(acc[1][ni], a[1], b);
            }
        }
        __syncthreads();
    }

    // deg reduce over tig quad; wc pair writes identical values (benign)
#pragma unroll
    for (int mi = 0; mi < 2; mi++)
#pragma unroll
        for (int r = 0; r < 2; r++) {
            float v = dg[mi][r];
            v += __shfl_xor_sync(0xffffffffu, v, 1);
            v += __shfl_xor_sync(0xffffffffu, v, 2);
            if (tig == 0) degs[wr * 32 + mi * 16 + r * 8 + g] = v;
        }
    __syncthreads();

    float inv[2][2];
#pragma unroll
    for (int mi = 0; mi < 2; mi++) {
        inv[mi][0] = 1.0f / degs[wr * 32 + mi * 16 + g];
        inv[mi][1] = 1.0f / degs[wr * 32 + mi * 16 + g + 8];
    }

#pragma unroll
    for (int ni = 0; ni < 8; ni++) {
        int col = wc * 64 + ni * 8 + tig * 2;
        float2 bv = *(const float2*)(bias + col);
#pragma unroll
        for (int mi = 0; mi < 2; mi++) {
            int row = m0 + wr * 32 + mi * 16 + g;
            float2 v0, v1;
            v0.x = leaky(fmaf(acc[mi][ni][0], inv[mi][0], bv.x));
            v0.y = leaky(fmaf(acc[mi][ni][1], inv[mi][0], bv.y));
            v1.x = leaky(fmaf(acc[mi][ni][2], inv[mi][1], bv.x));
            v1.y = leaky(fmaf(acc[mi][ni][3], inv[mi][1], bv.y));
            *(float2*)(out + ((size_t)bz * 1024 + row) * 128 + col) = v0;
            *(float2*)(out + ((size_t)bz * 1024 + row + 8) * 128 + col) = v1;
        }
    }
}

// ---------------- host ----------------
extern "C" void kernel_launch(void* const* d_in, const int* in_sizes, int n_in,
                              void* d_out, int out_size) {
    const float* X    = (const float*)d_in[0];  // [32,1024,128]
    const float* adj  = (const float*)d_in[1];  // [32,1024,1024]
    const float* W    = (const float*)d_in[2];  // [128,128]
    const float* bias = (const float*)d_in[3];  // [128]
    float* out = (float*)d_out;                 // [32,1024,128]

    static int inited = 0;
    if (!inited) {
        cudaFuncSetAttribute(k_xw, cudaFuncAttributeMaxDynamicSharedMemorySize, XW_SMEM);
        cudaFuncSetAttribute(k_main, cudaFuncAttributeMaxDynamicSharedMemorySize, MAIN_SMEM);
        inited = 1;
    }

    k_xw<<<512, 256, XW_SMEM>>>(X, W);
    k_main<<<dim3(8, 32), 256, MAIN_SMEM>>>(adj, bias, out);
}